// round 7
// baseline (speedup 1.0000x reference)
#include <cuda_runtime.h>
#include <cuda_bf16.h>

// out[b,n,m,f] = e0 + e1 * sigmoid((z - e2) * e3),  e = eta_fault[Mask[b,f]]
// sigmoid(x) = 0.5 + 0.5*tanh(0.5*x)  -> single MUFU.TANH per element.
// Folded per-(b,f):  s=0.5*e1 ; a=e0+s ; m=0.5*e3 ; d=e2*m
//   out = fma(s, tanh(fma(z, m, -d)), a)
//
// Persistent layout: exactly 148 SMs * 5 resident CTAs = 740 CTAs, one wave.
// Work = 262144 rows (of 256 floats) = 65536 tiles of 4 rows; grid-stride
// over tiles (88-89 tiles/CTA, +-1 imbalance) kills wave quantization.

#define B_DIM 8
#define N_DIM 64
#define M_DIM 512
#define F_DIM 256
#define N_ETA 15

constexpr int NBF        = B_DIM * F_DIM;              // 2048 (b,f) pairs
constexpr int F4         = F_DIM / 4;                  // 64 float4 per row
constexpr int THREADS    = 256;
constexpr int TOTAL_ROWS = B_DIM * N_DIM * M_DIM;      // 262144
constexpr int TILES      = TOTAL_ROWS / 4;             // 65536 (4 rows per tile)
constexpr int TILES_PER_B = TILES / B_DIM;             // 8192
constexpr int GRID       = 148 * 5;                    // 740 — one full wave

__device__ __forceinline__ float tanh_ap(float x) {
    float r;
    asm("tanh.approx.f32 %0, %1;" : "=f"(r) : "f"(x));
    return r;
}

__global__ __launch_bounds__(THREADS) void sigmoid_rt_persist(
    const float4* __restrict__ z,
    const void*   __restrict__ mask_raw,
    const float4* __restrict__ eta4,     // eta_fault viewed as [15] float4 rows
    float4*       __restrict__ out)
{
    const int fi   = threadIdx.x & (F4 - 1);   // float4 column (fixed per thread)
    const int rsub = threadIdx.x >> 6;         // row within the 4-row tile

    // ---- Mask dtype detection (int64 vs int32), warp-uniform ----
    // int32 view of the first 4KB is safe under both dtypes.
    // int64 (LE): odd words are high halves of values in [0,15) -> all zero.
    const int* m32 = (const int*)mask_raw;
    const long long* m64 = (const long long*)mask_raw;
    unsigned nz = __ballot_sync(0xffffffffu, m32[2 * threadIdx.x + 1] != 0);
    const bool is64 = (nz == 0u);

    // ---- Build the FULL folded coefficient table (all 2048 (b,f)) in smem ----
    __shared__ float4 s_coef[NBF];             // 32 KB
#pragma unroll
    for (int j = 0; j < NBF / THREADS; ++j) {
        const int k = j * THREADS + threadIdx.x;
        int idx = is64 ? (int)m64[k] : m32[k];
        idx = max(0, min(N_ETA - 1, idx));     // crash-proof under any dtype
        float4 e = eta4[idx];                  // (e0,e1,e2,e3)
        float s = 0.5f * e.y;
        float m = 0.5f * e.w;
        s_coef[k] = make_float4(s, e.x + s, m, e.z * m);
    }
    __syncthreads();

    // ---- Persistent grid-stride over 4-row tiles ----
#pragma unroll 4
    for (int t = blockIdx.x; t < TILES; t += GRID) {
        const int  b   = t / TILES_PER_B;                  // t >> 13
        const long row = ((long)t << 2) + rsub;            // global row index
        const float4* zp = z   + row * F4 + fi;
        float4*       op = out + row * F4 + fi;

        const int cb = (b << 8) + 4 * fi;                  // coef base for this tile
        float4 c0 = s_coef[cb + 0];
        float4 c1 = s_coef[cb + 1];
        float4 c2 = s_coef[cb + 2];
        float4 c3 = s_coef[cb + 3];

        float4 v = *zp;
        float4 r;
        r.x = fmaf(c0.x, tanh_ap(fmaf(v.x, c0.z, -c0.w)), c0.y);
        r.y = fmaf(c1.x, tanh_ap(fmaf(v.y, c1.z, -c1.w)), c1.y);
        r.z = fmaf(c2.x, tanh_ap(fmaf(v.z, c2.z, -c2.w)), c2.y);
        r.w = fmaf(c3.x, tanh_ap(fmaf(v.w, c3.z, -c3.w)), c3.y);
        *op = r;
    }
}

extern "C" void kernel_launch(void* const* d_in, const int* in_sizes, int n_in,
                              void* d_out, int out_size)
{
    // Bind inputs by element count — robust to metadata ordering.
    //   z = 67,108,864 ; Mask = 2,048 ; eta_fault = 60
    const float4* z    = nullptr;
    const void*   mask = nullptr;
    const float4* eta4 = nullptr;
    for (int i = 0; i < n_in; ++i) {
        if (in_sizes[i] > 1000000)   z    = (const float4*)d_in[i];
        else if (in_sizes[i] == NBF) mask = d_in[i];
        else                         eta4 = (const float4*)d_in[i];
    }

    sigmoid_rt_persist<<<GRID, THREADS>>>(z, mask, eta4, (float4*)d_out);
}

// round 8
// speedup vs baseline: 1.4882x; 1.4882x over previous
#include <cuda_runtime.h>
#include <cuda_bf16.h>

// out[b,n,m,f] = e0 + e1 * sigmoid((z - e2) * e3),  e = eta_fault[Mask[b,f]]
// sigmoid(x) = 0.5 + 0.5*tanh(0.5*x)  -> single MUFU.TANH per element.
// Folded per-(b,f):  s=0.5*e1 ; a=e0+s ; m=0.5*e3 ; d=e2*m
//   out = fma(s, tanh(fma(z, m, -d)), a)
//
// Single-wave grid: 8 batches x 92 blocks = 736 CTAs (occ limit ~740 = 148*5).
// b is FIXED per block -> coefficients stay in registers (R7 showed per-iter
// smem operand fetch makes L1 the bottleneck). Grid-stride within the batch.

#define B_DIM 8
#define N_DIM 64
#define M_DIM 512
#define F_DIM 256
#define N_ETA 15

constexpr int NBF         = B_DIM * F_DIM;            // 2048 (b,f) pairs
constexpr int F4          = F_DIM / 4;                // 64 float4 per row
constexpr int THREADS     = 256;
constexpr int ROWS_PER_B  = N_DIM * M_DIM;            // 32768
constexpr int TILES_PER_B = ROWS_PER_B / 4;           // 8192 four-row tiles
constexpr int BLKS_PER_B  = 92;                       // 8*92 = 736 CTAs ~ one wave

__device__ __forceinline__ float tanh_ap(float x) {
    float r;
    asm("tanh.approx.f32 %0, %1;" : "=f"(r) : "f"(x));
    return r;
}

__global__ __launch_bounds__(THREADS) void sigmoid_rt_wave(
    const float4* __restrict__ z,
    const void*   __restrict__ mask_raw,
    const float4* __restrict__ eta4,     // eta_fault viewed as [15] float4 rows
    float4*       __restrict__ out)
{
    const int b    = blockIdx.x / BLKS_PER_B;
    const int sub  = blockIdx.x % BLKS_PER_B;
    const int fi   = threadIdx.x & (F4 - 1);   // float4 column (fixed per thread)
    const int rsub = threadIdx.x >> 6;         // row within the 4-row tile

    // ---- Mask dtype detection (int64 vs int32), warp-uniform ----
    // int32 view of the first 4KB is safe under both dtypes.
    // int64 (LE): odd words are high halves of values in [0,15) -> all zero.
    const int* m32 = (const int*)mask_raw;
    const long long* m64 = (const long long*)mask_raw;
    unsigned nz = __ballot_sync(0xffffffffu, m32[2 * threadIdx.x + 1] != 0);
    const bool is64 = (nz == 0u);

    // ---- Prologue: stage this batch's folded quads through smem, then to regs ----
    __shared__ float4 s_coef[F_DIM];
    {
        const int k = b * F_DIM + threadIdx.x;     // (b, f=threadIdx.x)
        int idx = is64 ? (int)m64[k] : m32[k];
        idx = max(0, min(N_ETA - 1, idx));         // crash-proof under any dtype
        float4 e = eta4[idx];                      // one LDG.128: (e0,e1,e2,e3)
        float s = 0.5f * e.y;
        float m = 0.5f * e.w;
        s_coef[threadIdx.x] = make_float4(s, e.x + s, m, e.z * m);
    }
    __syncthreads();

    float4 c[4];
#pragma unroll
    for (int j = 0; j < 4; ++j)
        c[j] = s_coef[4 * fi + j];

    // ---- Grid-stride within this batch over 4-row tiles (register operands) ----
    const float4* zb = z   + (long)b * ROWS_PER_B * F4 + fi;
    float4*       ob = out + (long)b * ROWS_PER_B * F4 + fi;

#pragma unroll 4
    for (int t = sub; t < TILES_PER_B; t += BLKS_PER_B) {
        const long off = ((long)(4 * t + rsub)) * F4;
        float4 v = zb[off];
        float4 r;
        r.x = fmaf(c[0].x, tanh_ap(fmaf(v.x, c[0].z, -c[0].w)), c[0].y);
        r.y = fmaf(c[1].x, tanh_ap(fmaf(v.y, c[1].z, -c[1].w)), c[1].y);
        r.z = fmaf(c[2].x, tanh_ap(fmaf(v.z, c[2].z, -c[2].w)), c[2].y);
        r.w = fmaf(c[3].x, tanh_ap(fmaf(v.w, c[3].z, -c[3].w)), c[3].y);
        ob[off] = r;
    }
}

extern "C" void kernel_launch(void* const* d_in, const int* in_sizes, int n_in,
                              void* d_out, int out_size)
{
    // Bind inputs by element count — robust to metadata ordering.
    //   z = 67,108,864 ; Mask = 2,048 ; eta_fault = 60
    const float4* z    = nullptr;
    const void*   mask = nullptr;
    const float4* eta4 = nullptr;
    for (int i = 0; i < n_in; ++i) {
        if (in_sizes[i] > 1000000)   z    = (const float4*)d_in[i];
        else if (in_sizes[i] == NBF) mask = d_in[i];
        else                         eta4 = (const float4*)d_in[i];
    }

    sigmoid_rt_wave<<<B_DIM * BLKS_PER_B, THREADS>>>(z, mask, eta4, (float4*)d_out);
}

// round 9
// speedup vs baseline: 1.5523x; 1.0431x over previous
#include <cuda_runtime.h>
#include <cuda_bf16.h>

// out[b,n,m,f] = e0 + e1 * sigmoid((z - e2) * e3),  e = eta_fault[Mask[b,f]]
// sigmoid(x) = 0.5 + 0.5*tanh(0.5*x)  -> single MUFU.TANH per element.
// Folded per-(b,f):  s=0.5*e1 ; a=e0+s ; m=0.5*e3 ; d=e2*m
//   out = fma(s, tanh(fma(z, m, -d)), a)
//
// R6 structure (best: 77.3us kernel, 79.3% DRAM) with unroll 4 -> 8 to double
// per-thread MLP. b fixed per block; coefficients register-resident (R7 lesson).

#define B_DIM 8
#define N_DIM 64
#define M_DIM 512
#define F_DIM 256
#define N_ETA 15

constexpr int NBF           = B_DIM * F_DIM;             // 2048 (b,f) pairs
constexpr int ROWS_PER_B    = N_DIM * M_DIM;             // 32768 rows of 256 floats
constexpr int F4            = F_DIM / 4;                 // 64 float4 per row
constexpr int THREADS       = 256;
constexpr int ROWS_PER_ITER = THREADS / F4;              // 4
constexpr int BLOCKS_PER_B  = 256;
constexpr int ROWS_PER_BLK  = ROWS_PER_B / BLOCKS_PER_B; // 128 (contiguous per block)
constexpr int ITERS         = ROWS_PER_BLK / ROWS_PER_ITER; // 32

__device__ __forceinline__ float tanh_ap(float x) {
    float r;
    asm("tanh.approx.f32 %0, %1;" : "=f"(r) : "f"(x));
    return r;
}

__global__ __launch_bounds__(THREADS) void sigmoid_rt_fused(
    const float4* __restrict__ z,
    const void*   __restrict__ mask_raw,
    const float4* __restrict__ eta4,     // eta_fault viewed as [15] float4 rows
    float4*       __restrict__ out)
{
    const int b    = blockIdx.x / BLOCKS_PER_B;
    const int blk  = blockIdx.x % BLOCKS_PER_B;
    const int fi   = threadIdx.x & (F4 - 1);   // float4 column (fixed per thread)
    const int rsub = threadIdx.x >> 6;         // row within the 4-row group

    // ---- Mask dtype detection (int64 vs int32), warp-uniform ----
    // int32 view of the first 4KB is safe under both dtypes.
    // int64 (LE): odd words are high halves of values in [0,15) -> all zero.
    const int* m32 = (const int*)mask_raw;
    const long long* m64 = (const long long*)mask_raw;
    unsigned nz = __ballot_sync(0xffffffffu, m32[2 * threadIdx.x + 1] != 0);
    const bool is64 = (nz == 0u);

    // ---- Prologue: one folded quad per thread through smem, then 4 to regs ----
    __shared__ float4 s_coef[F_DIM];
    {
        const int k = b * F_DIM + threadIdx.x;     // (b, f=threadIdx.x)
        int idx = is64 ? (int)m64[k] : m32[k];
        idx = max(0, min(N_ETA - 1, idx));         // crash-proof under any dtype
        float4 e = eta4[idx];                      // one LDG.128: (e0,e1,e2,e3)
        float s = 0.5f * e.y;
        float m = 0.5f * e.w;
        s_coef[threadIdx.x] = make_float4(s, e.x + s, m, e.z * m);
    }
    __syncthreads();

    float4 c[4];
#pragma unroll
    for (int j = 0; j < 4; ++j)
        c[j] = s_coef[4 * fi + j];

    // ---- Main stream: contiguous 128-row block region, unroll 8 for MLP ----
    const long base_row = (long)b * ROWS_PER_B + (long)blk * ROWS_PER_BLK + rsub;
    const float4* zp = z   + base_row * F4 + fi;
    float4*       op = out + base_row * F4 + fi;
    const long stride = (long)ROWS_PER_ITER * F4;   // 256 float4 per step

#pragma unroll 8
    for (int it = 0; it < ITERS; ++it) {
        float4 v = zp[it * stride];
        float4 r;
        r.x = fmaf(c[0].x, tanh_ap(fmaf(v.x, c[0].z, -c[0].w)), c[0].y);
        r.y = fmaf(c[1].x, tanh_ap(fmaf(v.y, c[1].z, -c[1].w)), c[1].y);
        r.z = fmaf(c[2].x, tanh_ap(fmaf(v.z, c[2].z, -c[2].w)), c[2].y);
        r.w = fmaf(c[3].x, tanh_ap(fmaf(v.w, c[3].z, -c[3].w)), c[3].y);
        op[it * stride] = r;
    }
}

extern "C" void kernel_launch(void* const* d_in, const int* in_sizes, int n_in,
                              void* d_out, int out_size)
{
    // Bind inputs by element count — robust to metadata ordering.
    //   z = 67,108,864 ; Mask = 2,048 ; eta_fault = 60
    const float4* z    = nullptr;
    const void*   mask = nullptr;
    const float4* eta4 = nullptr;
    for (int i = 0; i < n_in; ++i) {
        if (in_sizes[i] > 1000000)   z    = (const float4*)d_in[i];
        else if (in_sizes[i] == NBF) mask = d_in[i];
        else                         eta4 = (const float4*)d_in[i];
    }

    sigmoid_rt_fused<<<B_DIM * BLOCKS_PER_B, THREADS>>>(z, mask, eta4, (float4*)d_out);
}

// round 10
// speedup vs baseline: 1.5932x; 1.0264x over previous
#include <cuda_runtime.h>
#include <cuda_bf16.h>

// out[b,n,m,f] = e0 + e1 * sigmoid((z - e2) * e3),  e = eta_fault[Mask[b,f]]
// sigmoid(x) = 0.5 + 0.5*tanh(0.5*x)  -> single MUFU.TANH per element.
// Folded per-(b,f):  s=0.5*e1 ; a=e0+s ; m=0.5*e3 ; d=e2*m
//   out = fma(s, tanh(fma(z, m, -d)), a)
//
// CONVERGED configuration (best of 7 measured variants, 86.1us):
//  - single fused kernel; 2048 blocks x 256 threads; 128 contiguous rows/block
//  - b fixed per block -> coefficients register-resident (smem only for prologue
//    staging; per-iter smem operands made L1 the bottleneck in R7)
//  - plain LDG/STG (streaming .cs hints cost 14% bandwidth in R5)
//  - unroll 4 (unroll 8 neutral-to-worse in R9); single-wave grids worse (R8)
//  - stream sustains ~6.3 TB/s = measured R/W-mix ceiling on this chip

#define B_DIM 8
#define N_DIM 64
#define M_DIM 512
#define F_DIM 256
#define N_ETA 15

constexpr int NBF           = B_DIM * F_DIM;             // 2048 (b,f) pairs
constexpr int ROWS_PER_B    = N_DIM * M_DIM;             // 32768 rows of 256 floats
constexpr int F4            = F_DIM / 4;                 // 64 float4 per row
constexpr int THREADS       = 256;
constexpr int ROWS_PER_ITER = THREADS / F4;              // 4
constexpr int BLOCKS_PER_B  = 256;
constexpr int ROWS_PER_BLK  = ROWS_PER_B / BLOCKS_PER_B; // 128 (contiguous per block)
constexpr int ITERS         = ROWS_PER_BLK / ROWS_PER_ITER; // 32

__device__ __forceinline__ float tanh_ap(float x) {
    float r;
    asm("tanh.approx.f32 %0, %1;" : "=f"(r) : "f"(x));
    return r;
}

__global__ __launch_bounds__(THREADS) void sigmoid_rt_fused(
    const float4* __restrict__ z,
    const void*   __restrict__ mask_raw,
    const float4* __restrict__ eta4,     // eta_fault viewed as [15] float4 rows
    float4*       __restrict__ out)
{
    const int b    = blockIdx.x / BLOCKS_PER_B;
    const int blk  = blockIdx.x % BLOCKS_PER_B;
    const int fi   = threadIdx.x & (F4 - 1);   // float4 column (fixed per thread)
    const int rsub = threadIdx.x >> 6;         // row within the 4-row group

    // ---- Mask dtype detection (int64 vs int32), warp-uniform ----
    // int32 view of the first 4KB is safe under both dtypes.
    // int64 (LE): odd words are high halves of values in [0,15) -> all zero.
    // int32: odd words random in [0,15); P(32 zeros) = 15^-32 ~ 0.
    const int* m32 = (const int*)mask_raw;
    const long long* m64 = (const long long*)mask_raw;
    unsigned nz = __ballot_sync(0xffffffffu, m32[2 * threadIdx.x + 1] != 0);
    const bool is64 = (nz == 0u);

    // ---- Prologue: one folded quad per thread through smem, then 4 to regs ----
    __shared__ float4 s_coef[F_DIM];
    {
        const int k = b * F_DIM + threadIdx.x;     // (b, f=threadIdx.x)
        int idx = is64 ? (int)m64[k] : m32[k];
        idx = max(0, min(N_ETA - 1, idx));         // crash-proof under any dtype
        float4 e = eta4[idx];                      // one LDG.128: (e0,e1,e2,e3)
        float s = 0.5f * e.y;
        float m = 0.5f * e.w;
        s_coef[threadIdx.x] = make_float4(s, e.x + s, m, e.z * m);
    }
    __syncthreads();

    float4 c[4];
#pragma unroll
    for (int j = 0; j < 4; ++j)
        c[j] = s_coef[4 * fi + j];

    // ---- Main stream: LDG.128 -> 2 FMA + TANH per lane -> STG.128 ----
    const long base_row = (long)b * ROWS_PER_B + (long)blk * ROWS_PER_BLK + rsub;
    const float4* zp = z   + base_row * F4 + fi;
    float4*       op = out + base_row * F4 + fi;
    const long stride = (long)ROWS_PER_ITER * F4;   // 256 float4 per step

#pragma unroll 4
    for (int it = 0; it < ITERS; ++it) {
        float4 v = zp[it * stride];
        float4 r;
        r.x = fmaf(c[0].x, tanh_ap(fmaf(v.x, c[0].z, -c[0].w)), c[0].y);
        r.y = fmaf(c[1].x, tanh_ap(fmaf(v.y, c[1].z, -c[1].w)), c[1].y);
        r.z = fmaf(c[2].x, tanh_ap(fmaf(v.z, c[2].z, -c[2].w)), c[2].y);
        r.w = fmaf(c[3].x, tanh_ap(fmaf(v.w, c[3].z, -c[3].w)), c[3].y);
        op[it * stride] = r;
    }
}

extern "C" void kernel_launch(void* const* d_in, const int* in_sizes, int n_in,
                              void* d_out, int out_size)
{
    // Bind inputs by element count — robust to metadata ordering.
    //   z = 67,108,864 ; Mask = 2,048 ; eta_fault = 60
    const float4* z    = nullptr;
    const void*   mask = nullptr;
    const float4* eta4 = nullptr;
    for (int i = 0; i < n_in; ++i) {
        if (in_sizes[i] > 1000000)   z    = (const float4*)d_in[i];
        else if (in_sizes[i] == NBF) mask = d_in[i];
        else                         eta4 = (const float4*)d_in[i];
    }

    sigmoid_rt_fused<<<B_DIM * BLOCKS_PER_B, THREADS>>>(z, mask, eta4, (float4*)d_out);
}